// round 3
// baseline (speedup 1.0000x reference)
#include <cuda_runtime.h>
#include <cstdint>

typedef unsigned long long u64;

__device__ double g_acc;
__device__ unsigned int g_count = 0;
// Pair-packed, lane-permuted reduced W2: [cp][idx], idx = 8*j + t,
// word = (W2r[2cp][o], W2r[2cp+1][o]) with o = 8*(t>>1) + 2*j + (t&1).
__device__ __align__(16) u64 g_W2p[8 * 32];

__device__ __forceinline__ void fma2(u64& d, u64 a, u64 b) {
    asm("fma.rn.f32x2 %0, %1, %2, %0;" : "+l"(d) : "l"(a), "l"(b));
}
__device__ __forceinline__ u64 pack2(float lo, float hi) {
    u64 r;
    asm("mov.b64 %0, {%1, %2};" : "=l"(r) : "f"(lo), "f"(hi));
    return r;
}
__device__ __forceinline__ float2 unpack2(u64 v) {
    float2 f;
    asm("mov.b64 {%0, %1}, %2;" : "=f"(f.x), "=f"(f.y) : "l"(v));
    return f;
}

// ---------------------------------------------------------------------------
// prep: W2 (16,256) -> reduced over v' -> pair-packed permuted (8cp x 32) u64.
// Folds 0.25 (1/sqrt(HID)) * sqrt(2) (post-relu scale). Zeroes g_acc.
// ---------------------------------------------------------------------------
__global__ void prep_kernel(const float* __restrict__ W2) {
    int tid = threadIdx.x;
    if (tid == 0) g_acc = 0.0;
    if (tid < 256) {
        int cp = tid >> 5;
        int idx = tid & 31;
        int j = idx >> 3;
        int t = idx & 7;
        int o = 8 * (t >> 1) + 2 * j + (t & 1);
        const float K = 0.35355339059327373f;
        float s0 = 0.f, s1 = 0.f;
        const float* p0 = W2 + (2 * cp) * 256 + o * 8;
        const float* p1 = W2 + (2 * cp + 1) * 256 + o * 8;
#pragma unroll
        for (int v = 0; v < 8; v++) { s0 += p0[v]; s1 += p1[v]; }
        g_W2p[cp * 32 + idx] = pack2(s0 * K, s1 * K);
    }
}

// ---------------------------------------------------------------------------
// edge kernel: 4 threads per edge (lane j handles u = 2j, 2j+1).
// contrib = sum_m x[m] * c[m]; everything lane-local, no shuffles.
// Finish (scale + write) fused via completion counter.
// ---------------------------------------------------------------------------
__global__ void __launch_bounds__(256)
edge_kernel(const float* __restrict__ feat, const float* __restrict__ evec,
            const float* __restrict__ W1, const int* __restrict__ esrc,
            float* __restrict__ out, int E) {
    __shared__ __align__(16) u64 sW2[256];   // [cp][8j + t]
    __shared__ __align__(16) u64 sW1[80];    // W1 rows as c-pairs: [basis][cp]
    __shared__ float sred[8];

    {
        int t = threadIdx.x;
        sW2[t] = g_W2p[t];
        if (t < 80) sW1[t] = ((const u64*)W1)[t];
    }
    __syncthreads();

    int tid = threadIdx.x;
    int j = tid & 3;
    int e = (blockIdx.x * 256 + tid) >> 2;
    float contrib = 0.f;

    if (e < E) {
        float ex = __ldg(evec + 3 * e + 0);
        float ey = __ldg(evec + 3 * e + 1);
        float ez = __ldg(evec + 3 * e + 2);
        float r = sqrtf(ex * ex + ey * ey + ez * ez);
        float inv_r = 1.0f / r;
        const float SQ3 = 1.7320508075688772f;
        float s1x = SQ3 * ex * inv_r;
        float s1y = SQ3 * ey * inv_r;
        float s1z = SQ3 * ez * inv_r;
        float S1 = s1x + s1y + s1z;

        // radial basis: centers at (jj+1)*step, step = 3/11; at most two
        // bases (floor(t)-1, floor(t)) are nonzero.
        const float inv_step = 11.0f / 3.0f;
        float tt = r * inv_step;
        int jb = (int)floorf(tt);
        int ja = jb - 1;
        float fa = 0.f, fb = 0.f;
        bool va = (ja >= 0) && (ja <= 9);
        bool vb = (jb >= 0) && (jb <= 9);
        if (va) {
            float diff = tt - (float)(ja + 1);
            float den = 1.0f - diff * diff;
            if (den > 0.f) fa = 1.14136f * __expf(2.0f - 2.0f / den);
        }
        if (vb) {
            float diff = tt - (float)(jb + 1);
            float den = 1.0f - diff * diff;
            if (den > 0.f) fb = 1.14136f * __expf(2.0f - 2.0f / den);
        }
        int ja_c = va ? ja : 0;
        int jb_c = vb ? jb : 0;

        // h = relu(f @ W1), pair-packed over hidden channel pairs.
        u64 fa2 = pack2(fa, fa);
        u64 fb2 = pack2(fb, fb);
        u64 h2[8];
#pragma unroll
        for (int cp = 0; cp < 8; cp++) {
            u64 a = 0ULL;
            fma2(a, fa2, sW1[ja_c * 8 + cp]);
            fma2(a, fb2, sW1[jb_c * 8 + cp]);
            float2 q = unpack2(a);
            h2[cp] = pack2(fmaxf(q.x, 0.f), fmaxf(q.y, 0.f));
        }

        // matvec: this lane's 8 outputs (groups A,B,C,D x u-pair), lanes of
        // each f32x2 accumulator hold even/odd hidden-channel partials.
        u64 acc[8];
#pragma unroll
        for (int k = 0; k < 8; k++) acc[k] = 0ULL;
#pragma unroll
        for (int cp = 0; cp < 8; cp++) {
            const u64* w = sW2 + cp * 32 + 8 * j;
            u64 hc = h2[cp];
#pragma unroll
            for (int k = 0; k < 8; k++) fma2(acc[k], hc, w[k]);
        }
        float ws[8];  // [2g+p]: g=0 A, 1 B, 2 C, 3 D; p -> u = 2j+p
#pragma unroll
        for (int k = 0; k < 8; k++) {
            float2 q = unpack2(acc[k]);
            ws[k] = q.x + q.y;
        }

        // gather this lane's 32B slice of the feature row (L2-resident).
        const float* row = feat + (size_t)__ldg(esrc + e) * 32;
        float2 sp  = *(const float2*)(row + 2 * j);        // s[u0], s[u1]
        const float* vb_p = row + 8 + 6 * j;
        float2 v01 = *(const float2*)(vb_p);               // v[u0].x, v[u0].y
        float2 v23 = *(const float2*)(vb_p + 2);           // v[u0].z, v[u1].x
        float2 v45 = *(const float2*)(vb_p + 4);           // v[u1].y, v[u1].z

        float vdot0 = v01.x * s1x + v01.y * s1y + v23.x * s1z;
        float vsum0 = v01.x + v01.y + v23.x;
        float vdot1 = v23.y * s1x + v45.x * s1y + v45.y * s1z;
        float vsum1 = v23.y + v45.x + v45.y;

        const float k3 = 0.5773502691896258f;
        contrib = sp.x * (ws[0] + S1 * ws[4]) + sp.y * (ws[1] + S1 * ws[5]) +
                  k3 * (ws[2] * vdot0 + ws[3] * vdot1) +
                  ws[6] * vsum0 + ws[7] * vsum1;
    }

    // warp -> block reduce -> one double atomic per block
#pragma unroll
    for (int off = 16; off > 0; off >>= 1)
        contrib += __shfl_down_sync(0xffffffffu, contrib, off);
    int lane = tid & 31;
    int warp = tid >> 5;
    if (lane == 0) sred[warp] = contrib;
    __syncthreads();
    if (warp == 0) {
        float v = (lane < 8) ? sred[lane] : 0.f;
#pragma unroll
        for (int off = 4; off > 0; off >>= 1)
            v += __shfl_down_sync(0xffffffffu, v, off);
        if (lane == 0) atomicAdd(&g_acc, (double)v);
    }

    // fused finish: last block writes the scaled scalar
    if (tid == 0) {
        __threadfence();
        unsigned int prev = atomicAdd(&g_count, 1u);
        if (prev == gridDim.x - 1) {
            double val = *((volatile double*)&g_acc);
            out[0] = (float)(val * 0.0625);  // 0.25 (pw) * 0.25 (1/sqrt(16))
            g_count = 0;
        }
    }
}

extern "C" void kernel_launch(void* const* d_in, const int* in_sizes, int n_in,
                              void* d_out, int out_size) {
    const float* feat = (const float*)d_in[0];  // (N, 32)
    const float* evec = (const float*)d_in[1];  // (E, 3)
    const float* W1   = (const float*)d_in[2];  // (10, 16)
    const float* W2   = (const float*)d_in[3];  // (16, 256)
    const int*   esrc = (const int*)d_in[4];    // (E,)
    // edge_dst / num_nodes drop out: segment_sum followed by total sum
    // == plain sum over edges.
    int E = in_sizes[4];

    prep_kernel<<<1, 256>>>(W2);
    int blocks = (E * 4 + 255) / 256;
    edge_kernel<<<blocks, 256>>>(feat, evec, W1, esrc, (float*)d_out, E);
}

// round 4
// speedup vs baseline: 4.0105x; 4.0105x over previous
#include <cuda_runtime.h>
#include <cstdint>

typedef unsigned long long u64;

#define MAXBLK 4096

__device__ double g_parts[MAXBLK];
__device__ __align__(16) float g_W2r[16 * 32];

__device__ __forceinline__ void fma2(u64& d, u64 a, u64 b) {
    asm("fma.rn.f32x2 %0, %1, %2, %0;" : "+l"(d) : "l"(a), "l"(b));
}
__device__ __forceinline__ u64 pack2(float lo, float hi) {
    u64 r;
    asm("mov.b64 %0, {%1, %2};" : "=l"(r) : "f"(lo), "f"(hi));
    return r;
}
__device__ __forceinline__ float2 unpack2(u64 v) {
    float2 f;
    asm("mov.b64 {%0, %1}, %2;" : "=f"(f.x), "=f"(f.y) : "l"(v));
    return f;
}

// ---------------------------------------------------------------------------
// prep: W2 (16,256) reduced over trailing v' -> W2r (16,32), folding
// 0.25 (1/sqrt(HID)) * sqrt(2) (post-relu scale).
// ---------------------------------------------------------------------------
__global__ void prep_kernel(const float* __restrict__ W2) {
    int tid = blockIdx.x * blockDim.x + threadIdx.x;
    if (tid < 512) {
        int c = tid >> 5;   // hid 0..15
        int o = tid & 31;   // (k*8+u) 0..31
        const float* p = W2 + c * 256 + o * 8;
        float s = 0.f;
#pragma unroll
        for (int v = 0; v < 8; v++) s += p[v];
        g_W2r[c * 32 + o] = s * 0.35355339059327373f;
    }
}

// ---------------------------------------------------------------------------
// edge kernel: one thread per edge. Warp-cooperative coalesced feature
// gather through an XOR-swizzled smem tile; broadcast-LDS 16x32 matvec as
// packed f32x2 FFMA2. Per-block partial -> plain store (NO global atomics).
// ---------------------------------------------------------------------------
__global__ void __launch_bounds__(256, 2)
edge_kernel(const float* __restrict__ feat, const float* __restrict__ evec,
            const float* __restrict__ W1, const int* __restrict__ esrc, int E) {
    __shared__ __align__(16) float4 tile[8][256];  // [warp][edge*8 + chunk]
    __shared__ __align__(16) float sW2r[512];
    __shared__ __align__(16) u64 sW1[80];
    __shared__ float sred[8];

    int tid = threadIdx.x;
    int lane = tid & 31;
    int wid = tid >> 5;

    for (int i = tid; i < 512; i += 256) sW2r[i] = g_W2r[i];
    if (tid < 80) sW1[tid] = ((const u64*)W1)[tid];
    __syncthreads();

    int e = blockIdx.x * 256 + tid;
    bool valid = e < E;
    int ec = valid ? e : 0;

    int myidx = __ldg(esrc + ec);

    // -------- cooperative coalesced gather into swizzled smem tile --------
    // instr k: lane loads float4 chunk (lane&7) of warp-edge (k*4 + lane>>3)
    float4* tw = tile[wid];
    int ch = lane & 7;
#pragma unroll
    for (int k = 0; k < 8; k++) {
        int esl = k * 4 + (lane >> 3);
        int idx = __shfl_sync(0xffffffffu, myidx, esl);
        tw[esl * 8 + (ch ^ (esl & 7))] =
            __ldg((const float4*)feat + (size_t)idx * 8 + ch);
    }

    // -------- per-edge radial / spherical work (overlaps the gather) ------
    float ex = __ldg(evec + 3 * ec + 0);
    float ey = __ldg(evec + 3 * ec + 1);
    float ez = __ldg(evec + 3 * ec + 2);
    float r = sqrtf(ex * ex + ey * ey + ez * ez);
    float inv_r = 1.0f / r;
    const float SQ3 = 1.7320508075688772f;
    float sh[3];
    sh[0] = SQ3 * ex * inv_r;
    sh[1] = SQ3 * ey * inv_r;
    sh[2] = SQ3 * ez * inv_r;
    float S1 = sh[0] + sh[1] + sh[2];

    // radial basis: centers at (j+1)*step, step = 3/11; at most two bases
    // (floor(t)-1, floor(t)) are nonzero for a given r.
    const float inv_step = 11.0f / 3.0f;
    float t = r * inv_step;
    int jb = (int)floorf(t);
    int ja = jb - 1;
    float fa = 0.f, fb = 0.f;
    bool va = (ja >= 0) && (ja <= 9);
    bool vbv = (jb >= 0) && (jb <= 9);
    if (va) {
        float diff = t - (float)(ja + 1);
        float den = 1.0f - diff * diff;
        if (den > 0.f) fa = 1.14136f * __expf(2.0f - 2.0f / den);
    }
    if (vbv) {
        float diff = t - (float)(jb + 1);
        float den = 1.0f - diff * diff;
        if (den > 0.f) fb = 1.14136f * __expf(2.0f - 2.0f / den);
    }
    int ja_c = va ? ja : 0;
    int jb_c = vbv ? jb : 0;

    // h = relu(f @ W1), pair-packed (sqrt(10) scales cancel exactly)
    u64 fa2 = pack2(fa, fa);
    u64 fb2 = pack2(fb, fb);
    float h[16];
#pragma unroll
    for (int cp = 0; cp < 8; cp++) {
        u64 a = 0ULL;
        fma2(a, fa2, sW1[ja_c * 8 + cp]);
        fma2(a, fb2, sW1[jb_c * 8 + cp]);
        float2 q = unpack2(a);
        h[2 * cp] = fmaxf(q.x, 0.f);
        h[2 * cp + 1] = fmaxf(q.y, 0.f);
    }

    // ws = h @ W2r : 16x32 matvec; weights broadcast from smem (1 wf/LDS)
    u64 acc[16];
#pragma unroll
    for (int j = 0; j < 16; j++) acc[j] = 0ULL;
#pragma unroll
    for (int c = 0; c < 16; c++) {
        u64 hc2 = pack2(h[c], h[c]);
        const ulonglong2* row = (const ulonglong2*)(sW2r + c * 32);
#pragma unroll
        for (int o = 0; o < 8; o++) {
            ulonglong2 p = row[o];
            fma2(acc[2 * o + 0], hc2, p.x);
            fma2(acc[2 * o + 1], hc2, p.y);
        }
    }
    float ws[32];
#pragma unroll
    for (int j = 0; j < 16; j++) {
        float2 q = unpack2(acc[j]);
        ws[2 * j] = q.x;
        ws[2 * j + 1] = q.y;
    }

    // combined coefficients: scalar coef cA[u], vector coef cB[u]*sh[i]+cD[u]
    const float k3 = 0.5773502691896258f;
    float cA[8], cB[8], cD[8];
#pragma unroll
    for (int u = 0; u < 8; u++) {
        cA[u] = ws[u] + S1 * ws[16 + u];
        cB[u] = k3 * ws[8 + u];
        cD[u] = ws[24 + u];
    }

    // -------- consume transposed feature row chunk-by-chunk --------
    __syncwarp();
    float contrib = 0.f;
#pragma unroll
    for (int k = 0; k < 8; k++) {
        float4 f = tw[lane * 8 + (k ^ ch)];
        float fv[4] = {f.x, f.y, f.z, f.w};
#pragma unroll
        for (int tt = 0; tt < 4; tt++) {
            int m = 4 * k + tt;
            if (m < 8) {
                contrib += fv[tt] * cA[m];
            } else {
                int vm = m - 8;
                int u = vm / 3;
                int i = vm - 3 * u;
                contrib += fv[tt] * (cB[u] * sh[i] + cD[u]);
            }
        }
    }
    if (!valid) contrib = 0.f;

    // -------- warp -> block reduce -> one plain store per block --------
#pragma unroll
    for (int off = 16; off > 0; off >>= 1)
        contrib += __shfl_down_sync(0xffffffffu, contrib, off);
    if (lane == 0) sred[wid] = contrib;
    __syncthreads();
    if (wid == 0) {
        float v = (lane < 8) ? sred[lane] : 0.f;
#pragma unroll
        for (int off = 4; off > 0; off >>= 1)
            v += __shfl_down_sync(0xffffffffu, v, off);
        if (lane == 0) g_parts[blockIdx.x] = (double)v;
    }
}

// ---------------------------------------------------------------------------
// finish: reduce per-block partials, apply 0.25 (pw) * 0.25 (1/sqrt(16))
// ---------------------------------------------------------------------------
__global__ void finish_kernel(float* out, int nparts) {
    __shared__ double sred[8];
    int tid = threadIdx.x;
    double s = 0.0;
    for (int i = tid; i < nparts; i += 256) s += g_parts[i];
#pragma unroll
    for (int off = 16; off > 0; off >>= 1)
        s += __shfl_down_sync(0xffffffffu, s, off);
    int lane = tid & 31, wid = tid >> 5;
    if (lane == 0) sred[wid] = s;
    __syncthreads();
    if (wid == 0) {
        double v = (lane < 8) ? sred[lane] : 0.0;
#pragma unroll
        for (int off = 4; off > 0; off >>= 1)
            v += __shfl_down_sync(0xffffffffu, v, off);
        if (lane == 0) out[0] = (float)(v * 0.0625);
    }
}

extern "C" void kernel_launch(void* const* d_in, const int* in_sizes, int n_in,
                              void* d_out, int out_size) {
    const float* feat = (const float*)d_in[0];  // (N, 32)
    const float* evec = (const float*)d_in[1];  // (E, 3)
    const float* W1   = (const float*)d_in[2];  // (10, 16)
    const float* W2   = (const float*)d_in[3];  // (16, 256)
    const int*   esrc = (const int*)d_in[4];    // (E,)
    // edge_dst / num_nodes drop out: segment_sum then total sum == sum
    // over edges.
    int E = in_sizes[4];

    int blocks = (E + 255) / 256;
    if (blocks > MAXBLK) blocks = MAXBLK;  // E=800k -> 3125, fits

    prep_kernel<<<2, 256>>>(W2);
    edge_kernel<<<blocks, 256>>>(feat, evec, W1, esrc, E);
    finish_kernel<<<1, 256>>>((float*)d_out, blocks);
}

// round 5
// speedup vs baseline: 5.3014x; 1.3219x over previous
#include <cuda_runtime.h>
#include <cstdint>

#define NB 2048
#define NROWS (NB + 2)
#define TPB 128
#define GRID_EDGE 740

__device__ double g_parts[1024];
__device__ unsigned int g_count = 0;
__device__ __align__(16) float g_LUT[NROWS * 32];

// ---------------------------------------------------------------------------
// prep: LUT[row][o] = ws_o(r=row*3/NB), the full radial pipeline
//   ws_k[u] = 0.0625 * 0.25 * (k==1 ? 1/sqrt(3) : 1) *
//             sum_c sqrt(2)*relu(sum_b f_b(r) W1[b][c]) * sum_v W2[c][k*64+u*8+v]
// Rows NB, NB+1 are zero (r >= MAX_RADIUS -> ws = 0).
// ---------------------------------------------------------------------------
__global__ void prep_kernel(const float* __restrict__ W1,
                            const float* __restrict__ W2) {
    __shared__ float sW2r[512];
    __shared__ float sW1[160];
    int tid = threadIdx.x;
    for (int q = tid; q < 512; q += TPB) {
        int c = q >> 5, o = q & 31;
        const float* p = W2 + c * 256 + o * 8;
        float s = 0.f;
#pragma unroll
        for (int v = 0; v < 8; v++) s += p[v];
        sW2r[q] = s;
    }
    for (int q = tid; q < 160; q += TPB) sW1[q] = W1[q];
    __syncthreads();

    int row = blockIdx.x * TPB + tid;
    if (row >= NROWS) return;
    float ws[32];
#pragma unroll
    for (int o = 0; o < 32; o++) ws[o] = 0.f;
    if (row < NB) {
        float r = row * (3.0f / NB);
        float f[10];
#pragma unroll
        for (int k = 0; k < 10; k++) {
            float c = (k + 1) * (3.0f / 11.0f);
            float d = (r - c) * (11.0f / 3.0f);
            float den = 1.0f - d * d;
            f[k] = (den > 0.f) ? 1.14136f * __expf(2.0f - 2.0f / den) : 0.f;
        }
        float h[16];
#pragma unroll
        for (int c = 0; c < 16; c++) {
            float s = 0.f;
#pragma unroll
            for (int k = 0; k < 10; k++) s += f[k] * sW1[k * 16 + c];
            h[c] = fmaxf(s, 0.f) * 1.4142135623730951f;
        }
#pragma unroll
        for (int c = 0; c < 16; c++) {
#pragma unroll
            for (int o = 0; o < 32; o++) ws[o] += h[c] * sW2r[c * 32 + o];
        }
        const float GS = 0.015625f;  // 0.25 (1/sqrt(HID)) * 0.0625 (pw * 1/sqrt(16))
        const float k3 = 0.5773502691896258f;
#pragma unroll
        for (int o = 0; o < 32; o++) {
            float sc = (o >= 8 && o < 16) ? GS * k3 : GS;
            ws[o] *= sc;
        }
    }
#pragma unroll
    for (int o = 0; o < 32; o++) g_LUT[row * 32 + o] = ws[o];
}

// ---------------------------------------------------------------------------
// edge kernel (persistent): per tile of 128 edges (1/thread):
//   phase 1: warp-cooperative gather of LUT rows i, i+1 (256B/edge) -> lerp
//   phase 2: warp-cooperative gather of feature row (128B/edge)     -> dot
// Block partial -> g_parts (plain store); last block reduces + writes out.
// ---------------------------------------------------------------------------
__global__ void __launch_bounds__(TPB, 5)
edge_kernel(const float* __restrict__ feat, const float* __restrict__ evec,
            const int* __restrict__ esrc, float* __restrict__ out,
            int E, int ntiles) {
    __shared__ __align__(16) float4 buf[4][2][256];  // [warp][A|B][slot] 32KB
    __shared__ double sredd[4];
    __shared__ int sflag;

    int tid = threadIdx.x;
    int lane = tid & 31;
    int wid = tid >> 5;
    int ch = lane & 7;
    float4* bA = buf[wid][0];
    float4* bB = buf[wid][1];

    double acc = 0.0;

    for (int tile = blockIdx.x; tile < ntiles; tile += gridDim.x) {
        int e = tile * TPB + wid * 32 + lane;
        bool valid = e < E;
        int ec = valid ? e : 0;

        float ex = __ldg(evec + 3 * ec + 0);
        float ey = __ldg(evec + 3 * ec + 1);
        float ez = __ldg(evec + 3 * ec + 2);
        int idx = __ldg(esrc + ec);

        float r = sqrtf(ex * ex + ey * ey + ez * ez);
        float inv_r = 1.0f / r;
        const float SQ3 = 1.7320508075688772f;
        float sh[3];
        sh[0] = SQ3 * ex * inv_r;
        sh[1] = SQ3 * ey * inv_r;
        sh[2] = SQ3 * ez * inv_r;
        float S1 = sh[0] + sh[1] + sh[2];

        float t = fminf(r * (NB / 3.0f), (float)NB);
        int irow = (int)t;
        float frac = t - (float)irow;

        // ---- phase 1: cooperative LUT gather (rows irow, irow+1) ----
#pragma unroll
        for (int k = 0; k < 8; k++) {
            int esl = k * 4 + (lane >> 3);
            int rr = __shfl_sync(0xffffffffu, irow, esl);
            const float4* base = ((const float4*)g_LUT) + rr * 8 + ch;
            int slot = esl * 8 + (ch ^ (esl & 7));
            bA[slot] = __ldg(base);
            bB[slot] = __ldg(base + 8);
        }
        __syncwarp();

        float L[32];
#pragma unroll
        for (int k = 0; k < 8; k++) {
            int slot = lane * 8 + (k ^ ch);
            float4 a = bA[slot];
            float4 b = bB[slot];
            L[4 * k + 0] = fmaf(frac, b.x - a.x, a.x);
            L[4 * k + 1] = fmaf(frac, b.y - a.y, a.y);
            L[4 * k + 2] = fmaf(frac, b.z - a.z, a.z);
            L[4 * k + 3] = fmaf(frac, b.w - a.w, a.w);
        }
        __syncwarp();

        // combined coefficients (k3 already folded into L[8..15])
        float cA[8], cB[8], cD[8];
#pragma unroll
        for (int u = 0; u < 8; u++) {
            cA[u] = L[u] + S1 * L[16 + u];
            cB[u] = L[8 + u];
            cD[u] = L[24 + u];
        }

        // ---- phase 2: cooperative feature gather (reuse bA) ----
#pragma unroll
        for (int k = 0; k < 8; k++) {
            int esl = k * 4 + (lane >> 3);
            int fi = __shfl_sync(0xffffffffu, idx, esl);
            bA[esl * 8 + (ch ^ (esl & 7))] =
                __ldg(((const float4*)feat) + (size_t)fi * 8 + ch);
        }
        __syncwarp();

        float contrib = 0.f;
#pragma unroll
        for (int k = 0; k < 8; k++) {
            float4 f4 = bA[lane * 8 + (k ^ ch)];
            float fv[4] = {f4.x, f4.y, f4.z, f4.w};
#pragma unroll
            for (int tt = 0; tt < 4; tt++) {
                int m = 4 * k + tt;
                if (m < 8) {
                    contrib += fv[tt] * cA[m];
                } else {
                    int vm = m - 8;
                    int u = vm / 3;
                    int i = vm - 3 * u;
                    contrib += fv[tt] * (cB[u] * sh[i] + cD[u]);
                }
            }
        }
        if (!valid) contrib = 0.f;

#pragma unroll
        for (int off = 16; off > 0; off >>= 1)
            contrib += __shfl_down_sync(0xffffffffu, contrib, off);
        if (lane == 0) acc += (double)contrib;
        __syncwarp();
    }

    // ---- block partial -> g_parts; last block reduces everything ----
    if (lane == 0) sredd[wid] = acc;
    __syncthreads();
    if (tid == 0) {
        g_parts[blockIdx.x] = sredd[0] + sredd[1] + sredd[2] + sredd[3];
        __threadfence();
        unsigned int prev = atomicAdd(&g_count, 1u);
        sflag = (prev == gridDim.x - 1) ? 1 : 0;
    }
    __syncthreads();
    if (sflag) {
        __threadfence();
        double s = 0.0;
        for (int i = tid; i < gridDim.x; i += TPB)
            s += ((volatile double*)g_parts)[i];
#pragma unroll
        for (int off = 16; off > 0; off >>= 1)
            s += __shfl_down_sync(0xffffffffu, s, off);
        __shared__ double fin[4];
        if (lane == 0) fin[wid] = s;
        __syncthreads();
        if (tid == 0) {
            out[0] = (float)(fin[0] + fin[1] + fin[2] + fin[3]);
            g_count = 0;
        }
    }
}

extern "C" void kernel_launch(void* const* d_in, const int* in_sizes, int n_in,
                              void* d_out, int out_size) {
    const float* feat = (const float*)d_in[0];  // (N, 32)
    const float* evec = (const float*)d_in[1];  // (E, 3)
    const float* W1   = (const float*)d_in[2];  // (10, 16)
    const float* W2   = (const float*)d_in[3];  // (16, 256)
    const int*   esrc = (const int*)d_in[4];    // (E,)
    // edge_dst / num_nodes drop out: segment_sum then total sum == sum over
    // edges; the radial pipeline collapses to a 1-D LUT in r.
    int E = in_sizes[4];
    int ntiles = (E + TPB - 1) / TPB;

    prep_kernel<<<(NROWS + TPB - 1) / TPB, TPB>>>(W1, W2);
    edge_kernel<<<GRID_EDGE, TPB>>>(feat, evec, esrc, (float*)d_out, E, ntiles);
}